// round 1
// baseline (speedup 1.0000x reference)
#include <cuda_runtime.h>
#include <math.h>

#define B_   8
#define T_   2048
#define DIM_ 512
#define NH_  8
#define NKV_ 4
#define HD_  64
#define KVD_ 256
#define BT_  (B_ * T_)

// Scratch (static device allocations are allowed; runtime alloc is not)
__device__ float g_q[BT_ * DIM_];   // [B,T,NH*HD]  token-major
__device__ float g_k[BT_ * KVD_];   // [B,T,NKV*HD]
__device__ float g_v[BT_ * KVD_];
__device__ float g_y[BT_ * DIM_];   // attention output, token-major head-concat

// ---------------------------------------------------------------------------
// Generic SGEMM: C[M,N] = A[M,K] * B[N,K]^T   (both row-major, dot of rows)
// 64x64 tile, 256 threads, 4x4 per-thread microtile, BK=16
// ---------------------------------------------------------------------------
__global__ __launch_bounds__(256) void sgemm_nt(const float* __restrict__ A,
                                                const float* __restrict__ Bm,
                                                float* __restrict__ C,
                                                int M, int N, int K) {
    __shared__ float As[16][68];   // [k][m]
    __shared__ float Bs[16][68];   // [k][n]
    const int tid = threadIdx.x;
    const int tx = tid & 15;       // 0..15
    const int ty = tid >> 4;       // 0..15
    const int bm = blockIdx.y << 6;
    const int bn = blockIdx.x << 6;

    float acc[4][4];
#pragma unroll
    for (int i = 0; i < 4; i++)
#pragma unroll
        for (int j = 0; j < 4; j++) acc[i][j] = 0.f;

    for (int k0 = 0; k0 < K; k0 += 16) {
#pragma unroll
        for (int i = 0; i < 4; i++) {
            int row = ty + 16 * i;
            As[tx][row] = A[(size_t)(bm + row) * K + k0 + tx];
            Bs[tx][row] = Bm[(size_t)(bn + row) * K + k0 + tx];
        }
        __syncthreads();
#pragma unroll
        for (int kk = 0; kk < 16; kk++) {
            float a[4], b[4];
#pragma unroll
            for (int i = 0; i < 4; i++) a[i] = As[kk][ty * 4 + i];
#pragma unroll
            for (int j = 0; j < 4; j++) b[j] = Bs[kk][tx * 4 + j];
#pragma unroll
            for (int i = 0; i < 4; i++)
#pragma unroll
                for (int j = 0; j < 4; j++)
                    acc[i][j] = fmaf(a[i], b[j], acc[i][j]);
        }
        __syncthreads();
    }
#pragma unroll
    for (int i = 0; i < 4; i++)
#pragma unroll
        for (int j = 0; j < 4; j++)
            C[(size_t)(bm + ty * 4 + i) * N + bn + tx * 4 + j] = acc[i][j];
}

// ---------------------------------------------------------------------------
// RMSNorm (per head, HD=64) + RoPE, in place on g_q / g_k.
// One warp per (token, head). Lane i owns the (i, i+32) rotation pair.
// ---------------------------------------------------------------------------
__global__ void rmsrope_kernel(float* __restrict__ q, float* __restrict__ k) {
    const int token = blockIdx.x;           // 0..BT-1
    const int head  = blockIdx.y;           // 0..NH+NKV-1
    const int lane  = threadIdx.x;          // 0..31
    const int t     = token & (T_ - 1);

    float* base = (head < NH_)
        ? q + (size_t)token * DIM_ + head * HD_
        : k + (size_t)token * KVD_ + (head - NH_) * HD_;

    float x1 = base[lane];
    float x2 = base[lane + 32];
    float ss = x1 * x1 + x2 * x2;
#pragma unroll
    for (int o = 16; o; o >>= 1) ss += __shfl_xor_sync(0xffffffffu, ss, o);
    const float r = rsqrtf(ss * (1.0f / 64.0f) + 1.1920928955078125e-07f);
    x1 *= r; x2 *= r;

    // angle in double: removes any table-accuracy concern at large t
    double inv = pow(10000.0, -(double)(2 * lane) / 64.0);
    double f   = (double)t * inv;
    float c = (float)cos(f);
    float s = (float)sin(f);

    base[lane]      =  x1 * c + x2 * s;
    base[lane + 32] = -x1 * s + x2 * c;
}

// ---------------------------------------------------------------------------
// Flash-style causal attention. One block = (b,h, 64-query tile).
// 128 threads: ty=tid>>3 owns 4 q-rows, tx=tid&7 owns 8 cols.
// smem: Qs[row][d], KsT[d][kvrow] (transposed -> conflict-free Sᵀ reads),
//       Vs[kvrow][d], Ps[qrow][kvrow]; all stride 68.
// ---------------------------------------------------------------------------
#define ATT_SMEM (4 * 64 * 68 * (int)sizeof(float))

__global__ __launch_bounds__(128) void attn_kernel(const float* __restrict__ q,
                                                   const float* __restrict__ k,
                                                   const float* __restrict__ v,
                                                   float* __restrict__ y) {
    extern __shared__ float sm[];
    float* Qs  = sm;
    float* KsT = sm + 64 * 68;
    float* Vs  = sm + 2 * 64 * 68;
    float* Ps  = sm + 3 * 64 * 68;

    const int tid = threadIdx.x;
    const int tx = tid & 7;
    const int ty = tid >> 3;
    const int bh = blockIdx.x;
    const int b  = bh >> 3;
    const int h  = bh & 7;
    const int hk = h >> 1;                 // GQA 2:1
    const int q0 = blockIdx.y << 6;

    const float* qb = q + ((size_t)(b * T_ + q0)) * DIM_ + h * HD_;
    const float* kb = k + ((size_t)(b * T_)) * KVD_ + hk * HD_;
    const float* vb = v + ((size_t)(b * T_)) * KVD_ + hk * HD_;

    // load Q tile
    for (int i = tid; i < 64 * 16; i += 128) {
        int rr = i >> 4, c4 = (i & 15) << 2;
        *(float4*)(Qs + rr * 68 + c4) = *(const float4*)(qb + (size_t)rr * DIM_ + c4);
    }

    float m_[4], l_[4], o_[4][8];
#pragma unroll
    for (int i = 0; i < 4; i++) {
        m_[i] = -3.0e38f; l_[i] = 0.f;
#pragma unroll
        for (int j = 0; j < 8; j++) o_[i][j] = 0.f;
    }

    const int ntiles = blockIdx.y + 1;
    for (int kt = 0; kt < ntiles; kt++) {
        const int k0 = kt << 6;
        __syncthreads();   // prior PV reads of Vs done; also orders Q load (1st iter)
        for (int i = tid; i < 64 * 16; i += 128) {
            int rr = i >> 4, c4 = (i & 15) << 2;
            float4 kk4 = *(const float4*)(kb + (size_t)(k0 + rr) * KVD_ + c4);
            KsT[(c4 + 0) * 68 + rr] = kk4.x;
            KsT[(c4 + 1) * 68 + rr] = kk4.y;
            KsT[(c4 + 2) * 68 + rr] = kk4.z;
            KsT[(c4 + 3) * 68 + rr] = kk4.w;
            *(float4*)(Vs + rr * 68 + c4) = *(const float4*)(vb + (size_t)(k0 + rr) * KVD_ + c4);
        }
        __syncthreads();

        // S = Q K^T
        float s_[4][8];
#pragma unroll
        for (int i = 0; i < 4; i++)
#pragma unroll
            for (int j = 0; j < 8; j++) s_[i][j] = 0.f;

#pragma unroll 8
        for (int d = 0; d < 64; d++) {
            float a[4], bb[8];
#pragma unroll
            for (int i = 0; i < 4; i++) a[i] = Qs[(ty * 4 + i) * 68 + d];
#pragma unroll
            for (int j = 0; j < 8; j++) bb[j] = KsT[d * 68 + tx * 8 + j];
#pragma unroll
            for (int i = 0; i < 4; i++)
#pragma unroll
                for (int j = 0; j < 8; j++)
                    s_[i][j] = fmaf(a[i], bb[j], s_[i][j]);
        }

        const bool diag = (kt == (ntiles - 1));
#pragma unroll
        for (int i = 0; i < 4; i++) {
            const int rg = q0 + ty * 4 + i;
            float mloc = -3.0e38f;
#pragma unroll
            for (int j = 0; j < 8; j++) {
                float sv = s_[i][j] * 0.125f;
                if (diag && (k0 + tx * 8 + j > rg)) sv = -3.0e38f;
                s_[i][j] = sv;
                mloc = fmaxf(mloc, sv);
            }
            mloc = fmaxf(mloc, __shfl_xor_sync(0xffffffffu, mloc, 1));
            mloc = fmaxf(mloc, __shfl_xor_sync(0xffffffffu, mloc, 2));
            mloc = fmaxf(mloc, __shfl_xor_sync(0xffffffffu, mloc, 4));
            const float mnew  = fmaxf(m_[i], mloc);
            const float alpha = expf(m_[i] - mnew);
            m_[i] = mnew;
            float sum = 0.f;
#pragma unroll
            for (int j = 0; j < 8; j++) {
                float pv = expf(s_[i][j] - mnew);
                s_[i][j] = pv;
                sum += pv;
            }
            sum += __shfl_xor_sync(0xffffffffu, sum, 1);
            sum += __shfl_xor_sync(0xffffffffu, sum, 2);
            sum += __shfl_xor_sync(0xffffffffu, sum, 4);
            l_[i] = l_[i] * alpha + sum;
#pragma unroll
            for (int j = 0; j < 8; j++) o_[i][j] *= alpha;
#pragma unroll
            for (int j = 0; j < 8; j++) Ps[(ty * 4 + i) * 68 + tx * 8 + j] = s_[i][j];
        }
        __syncthreads();

        // O += P V
#pragma unroll 8
        for (int d = 0; d < 64; d++) {
            float a[4], bb[8];
#pragma unroll
            for (int i = 0; i < 4; i++) a[i] = Ps[(ty * 4 + i) * 68 + d];
#pragma unroll
            for (int j = 0; j < 8; j++) bb[j] = Vs[d * 68 + tx * 8 + j];
#pragma unroll
            for (int i = 0; i < 4; i++)
#pragma unroll
                for (int j = 0; j < 8; j++)
                    o_[i][j] = fmaf(a[i], bb[j], o_[i][j]);
        }
    }

#pragma unroll
    for (int i = 0; i < 4; i++) {
        const float inv = 1.0f / l_[i];
        const size_t row = (size_t)(b * T_ + q0 + ty * 4 + i);
#pragma unroll
        for (int j = 0; j < 8; j++)
            y[row * DIM_ + h * HD_ + tx * 8 + j] = o_[i][j] * inv;
    }
}

// ---------------------------------------------------------------------------
extern "C" void kernel_launch(void* const* d_in, const int* in_sizes, int n_in,
                              void* d_out, int out_size) {
    const float* x  = (const float*)d_in[0];
    const float* Wq = (const float*)d_in[1];
    const float* Wk = (const float*)d_in[2];
    const float* Wv = (const float*)d_in[3];
    const float* Wp = (const float*)d_in[4];
    float* out = (float*)d_out;

    float *pq, *pk, *pv, *py;
    cudaGetSymbolAddress((void**)&pq, g_q);
    cudaGetSymbolAddress((void**)&pk, g_k);
    cudaGetSymbolAddress((void**)&pv, g_v);
    cudaGetSymbolAddress((void**)&py, g_y);

    cudaFuncSetAttribute(attn_kernel, cudaFuncAttributeMaxDynamicSharedMemorySize,
                         ATT_SMEM);

    dim3 gq(DIM_ / 64, BT_ / 64);
    dim3 gkv(KVD_ / 64, BT_ / 64);

    sgemm_nt<<<gq, 256>>>(x, Wq, pq, BT_, DIM_, DIM_);
    sgemm_nt<<<gkv, 256>>>(x, Wk, pk, BT_, KVD_, DIM_);
    sgemm_nt<<<gkv, 256>>>(x, Wv, pv, BT_, KVD_, DIM_);

    rmsrope_kernel<<<dim3(BT_, NH_ + NKV_), 32>>>(pq, pk);

    attn_kernel<<<dim3(B_ * NH_, T_ / 64), 128, ATT_SMEM>>>(pq, pk, pv, py);

    sgemm_nt<<<gq, 256>>>(py, Wp, out, BT_, DIM_, DIM_);
}

// round 4
// speedup vs baseline: 3.0698x; 3.0698x over previous
#include <cuda_runtime.h>
#include <math.h>
#include <stdint.h>

#define B_   8
#define T_   2048
#define DIM_ 512
#define NH_  8
#define NKV_ 4
#define HD_  64
#define KVD_ 256
#define BT_  (B_ * T_)

__device__ float g_q[BT_ * DIM_];
__device__ float g_k[BT_ * KVD_];
__device__ float g_v[BT_ * KVD_];
__device__ float g_y[BT_ * DIM_];

// ---------------------------------------------------------------------------
// mma.sync m16n8k8 tf32 helpers
// ---------------------------------------------------------------------------
__device__ __forceinline__ uint32_t f2tf32(float x) {
    uint32_t r;
    asm("cvt.rna.tf32.f32 %0, %1;" : "=r"(r) : "f"(x));
    return r;
}
__device__ __forceinline__ void mma_tf32(float* c, uint32_t a0, uint32_t a1,
                                         uint32_t a2, uint32_t a3,
                                         uint32_t b0, uint32_t b1) {
    asm volatile(
        "mma.sync.aligned.m16n8k8.row.col.f32.tf32.tf32.f32 "
        "{%0,%1,%2,%3}, {%4,%5,%6,%7}, {%8,%9}, {%0,%1,%2,%3};"
        : "+f"(c[0]), "+f"(c[1]), "+f"(c[2]), "+f"(c[3])
        : "r"(a0), "r"(a1), "r"(a2), "r"(a3), "r"(b0), "r"(b1));
}
__device__ __forceinline__ uint32_t ldb(const float* p) {
    return __float_as_uint(*p);
}

// ---------------------------------------------------------------------------
// Tensor-core tf32 GEMM: C[M,N] = A[M,K] * B[N,K]^T.  CTA 128x128, K-chunk 32.
// 256 threads, 8 warps (2m x 4n), warp tile 64x32. Double-buffered smem.
// smem stride 36 floats -> conflict-free fragment loads.
// ---------------------------------------------------------------------------
#define GST 36
#define GEMM_SMEM (4 * 128 * GST * 4)   // 2 stages * (A + B) = 73728 B

__global__ __launch_bounds__(256) void gemm_mma(const float* __restrict__ A,
                                                const float* __restrict__ Bm,
                                                float* __restrict__ C,
                                                int M, int N, int K) {
    extern __shared__ float sm[];
    const int tid  = threadIdx.x;
    const int warp = tid >> 5;
    const int lane = tid & 31;
    const int gid  = lane >> 2;     // 0..7
    const int qid  = lane & 3;      // 0..3
    const int bm = blockIdx.y << 7;
    const int bn = blockIdx.x << 7;
    const int wm = (warp >> 2) << 6;   // 0 or 64
    const int wn = (warp & 3) << 5;    // 0,32,64,96

    float acc[4][4][4];
#pragma unroll
    for (int mt = 0; mt < 4; mt++)
#pragma unroll
        for (int nt = 0; nt < 4; nt++)
#pragma unroll
            for (int r = 0; r < 4; r++) acc[mt][nt][r] = 0.f;

    const int nch = K >> 5;
    float4 ra[4], rb[4];

    // prologue: chunk 0
#pragma unroll
    for (int i = 0; i < 4; i++) {
        const int idx = (i << 8) + tid, row = idx >> 3, c4 = (idx & 7) << 2;
        ra[i] = *(const float4*)(A  + (size_t)(bm + row) * K + c4);
        rb[i] = *(const float4*)(Bm + (size_t)(bn + row) * K + c4);
    }
    {
        float* As = sm; float* Bs = sm + 128 * GST;
#pragma unroll
        for (int i = 0; i < 4; i++) {
            const int idx = (i << 8) + tid, row = idx >> 3, c4 = (idx & 7) << 2;
            uint4 ua = { f2tf32(ra[i].x), f2tf32(ra[i].y), f2tf32(ra[i].z), f2tf32(ra[i].w) };
            uint4 ub = { f2tf32(rb[i].x), f2tf32(rb[i].y), f2tf32(rb[i].z), f2tf32(rb[i].w) };
            *(uint4*)(As + row * GST + c4) = ua;
            *(uint4*)(Bs + row * GST + c4) = ub;
        }
    }
    __syncthreads();

    for (int kc = 0; kc < nch; kc++) {
        if (kc + 1 < nch) {
            const int k0 = (kc + 1) << 5;
#pragma unroll
            for (int i = 0; i < 4; i++) {
                const int idx = (i << 8) + tid, row = idx >> 3, c4 = (idx & 7) << 2;
                ra[i] = *(const float4*)(A  + (size_t)(bm + row) * K + k0 + c4);
                rb[i] = *(const float4*)(Bm + (size_t)(bn + row) * K + k0 + c4);
            }
        }
        {
            const float* As = sm + (kc & 1) * (2 * 128 * GST);
            const float* Bs = As + 128 * GST;
#pragma unroll
            for (int ks = 0; ks < 4; ks++) {
                uint32_t af[4][4], bf[4][2];
#pragma unroll
                for (int mt = 0; mt < 4; mt++) {
                    const float* ap = As + (wm + mt * 16 + gid) * GST + ks * 8 + qid;
                    af[mt][0] = ldb(ap);
                    af[mt][1] = ldb(ap + 8 * GST);
                    af[mt][2] = ldb(ap + 4);
                    af[mt][3] = ldb(ap + 8 * GST + 4);
                }
#pragma unroll
                for (int nt = 0; nt < 4; nt++) {
                    const float* bp = Bs + (wn + nt * 8 + gid) * GST + ks * 8 + qid;
                    bf[nt][0] = ldb(bp);
                    bf[nt][1] = ldb(bp + 4);
                }
#pragma unroll
                for (int mt = 0; mt < 4; mt++)
#pragma unroll
                    for (int nt = 0; nt < 4; nt++)
                        mma_tf32(acc[mt][nt], af[mt][0], af[mt][1], af[mt][2], af[mt][3],
                                 bf[nt][0], bf[nt][1]);
            }
        }
        if (kc + 1 < nch) {
            __syncthreads();
            float* As = sm + ((kc + 1) & 1) * (2 * 128 * GST);
            float* Bs = As + 128 * GST;
#pragma unroll
            for (int i = 0; i < 4; i++) {
                const int idx = (i << 8) + tid, row = idx >> 3, c4 = (idx & 7) << 2;
                uint4 ua = { f2tf32(ra[i].x), f2tf32(ra[i].y), f2tf32(ra[i].z), f2tf32(ra[i].w) };
                uint4 ub = { f2tf32(rb[i].x), f2tf32(rb[i].y), f2tf32(rb[i].z), f2tf32(rb[i].w) };
                *(uint4*)(As + row * GST + c4) = ua;
                *(uint4*)(Bs + row * GST + c4) = ub;
            }
            __syncthreads();
        }
    }

    // epilogue: float2 stores
#pragma unroll
    for (int mt = 0; mt < 4; mt++) {
        const int r0 = bm + wm + mt * 16 + gid;
#pragma unroll
        for (int nt = 0; nt < 4; nt++) {
            const int cc = bn + wn + nt * 8 + 2 * qid;
            *(float2*)(C + (size_t)r0 * N + cc)       = make_float2(acc[mt][nt][0], acc[mt][nt][1]);
            *(float2*)(C + (size_t)(r0 + 8) * N + cc) = make_float2(acc[mt][nt][2], acc[mt][nt][3]);
        }
    }
}

// ---------------------------------------------------------------------------
// RMSNorm + RoPE (fp32, constant inv_freq table).
// ---------------------------------------------------------------------------
__constant__ float c_invfreq[32] = {
    1.0f, 0.7498942093324559f, 0.5623413251903491f, 0.4216965034285822f,
    0.31622776601683794f, 0.23713737056616552f, 0.1778279410038923f, 0.13335214321633242f,
    0.1f, 0.07498942093324558f, 0.05623413251903491f, 0.04216965034285822f,
    0.031622776601683794f, 0.023713737056616554f, 0.01778279410038923f, 0.013335214321633242f,
    0.01f, 0.007498942093324559f, 0.005623413251903491f, 0.004216965034285823f,
    0.0031622776601683794f, 0.0023713737056616554f, 0.001778279410038923f, 0.0013335214321633242f,
    0.001f, 0.0007498942093324558f, 0.0005623413251903491f, 0.0004216965034285822f,
    0.00031622776601683794f, 0.00023713737056616552f, 0.0001778279410038923f, 0.00013335214321633242f
};

__global__ __launch_bounds__(256) void rmsrope_kernel(float* __restrict__ q,
                                                      float* __restrict__ k) {
    const int lane = threadIdx.x & 31;
    const int token = (blockIdx.x << 3) + (threadIdx.x >> 5);
    const int head = blockIdx.y;
    const int t = token & (T_ - 1);

    float* base = (head < NH_)
        ? q + (size_t)token * DIM_ + head * HD_
        : k + (size_t)token * KVD_ + (head - NH_) * HD_;

    float x1 = base[lane];
    float x2 = base[lane + 32];
    float ss = x1 * x1 + x2 * x2;
#pragma unroll
    for (int o = 16; o; o >>= 1) ss += __shfl_xor_sync(0xffffffffu, ss, o);
    const float r = rsqrtf(ss * (1.0f / 64.0f) + 1.1920928955078125e-07f);
    x1 *= r; x2 *= r;

    const float f = (float)t * c_invfreq[lane];
    float s, c;
    sincosf(f, &s, &c);

    base[lane]      =  x1 * c + x2 * s;
    base[lane + 32] = -x1 * s + x2 * c;
}

// ---------------------------------------------------------------------------
// Flash attention, tensor-core tf32. 256 threads (8 warps), q-tile 128,
// kv-tile 64. Warp w owns q rows [16w, 16w+16). smem values are tf32 bits.
// ---------------------------------------------------------------------------
#define AST 68
#define ATT_SMEM ((128 + 64 + 64 + 128) * AST * 4)   // Qs,KsT,Vs,Ps = 104448 B

__global__ __launch_bounds__(256) void attn_kernel(const float* __restrict__ q,
                                                   const float* __restrict__ k,
                                                   const float* __restrict__ v,
                                                   float* __restrict__ y) {
    extern __shared__ float sm[];
    float* Qs  = sm;                       // [128][AST]
    float* KsT = Qs + 128 * AST;           // [64 d][AST kv]
    float* Vs  = KsT + 64 * AST;           // [64 kv][AST d]
    float* Ps  = Vs + 64 * AST;            // [128][AST kv]

    const int tid  = threadIdx.x;
    const int warp = tid >> 5;
    const int lane = tid & 31;
    const int gid  = lane >> 2;
    const int qid  = lane & 3;
    const int bh = blockIdx.x;
    const int b  = bh >> 3;
    const int h  = bh & 7;
    const int hk = h >> 1;
    const int q0 = blockIdx.y << 7;

    const float* qb = q + ((size_t)(b * T_ + q0)) * DIM_ + h * HD_;
    const float* kb = k + ((size_t)(b * T_)) * KVD_ + hk * HD_;
    const float* vb = v + ((size_t)(b * T_)) * KVD_ + hk * HD_;

    // Q tile (tf32 bits)
#pragma unroll
    for (int i = 0; i < 8; i++) {
        const int idx = (i << 8) + tid;
        const int rr = idx >> 4, c4 = (idx & 15) << 2;
        float4 vq = *(const float4*)(qb + (size_t)rr * DIM_ + c4);
        uint4 uq = { f2tf32(vq.x), f2tf32(vq.y), f2tf32(vq.z), f2tf32(vq.w) };
        *(uint4*)(Qs + rr * AST + c4) = uq;
    }

    const int row0 = q0 + warp * 16 + gid;     // global q row for c0/c1
    float m_[2], l_[2], o_[8][4];
    m_[0] = m_[1] = -1e30f;
    l_[0] = l_[1] = 0.f;
#pragma unroll
    for (int nt = 0; nt < 8; nt++)
#pragma unroll
        for (int r = 0; r < 4; r++) o_[nt][r] = 0.f;

    const int ntiles = 2 * (blockIdx.y + 1);
    for (int kt = 0; kt < ntiles; kt++) {
        const int k0 = kt << 6;
        __syncthreads();   // prior PV reads done; Q tile done (iter 0)
#pragma unroll
        for (int i = 0; i < 4; i++) {
            const int idx = (i << 8) + tid;
            const int rr = idx >> 4, c4 = (idx & 15) << 2;
            float4 kk4 = *(const float4*)(kb + (size_t)(k0 + rr) * KVD_ + c4);
            KsT[(c4 + 0) * AST + rr] = __uint_as_float(f2tf32(kk4.x));
            KsT[(c4 + 1) * AST + rr] = __uint_as_float(f2tf32(kk4.y));
            KsT[(c4 + 2) * AST + rr] = __uint_as_float(f2tf32(kk4.z));
            KsT[(c4 + 3) * AST + rr] = __uint_as_float(f2tf32(kk4.w));
            float4 vv4 = *(const float4*)(vb + (size_t)(k0 + rr) * KVD_ + c4);
            uint4 uv = { f2tf32(vv4.x), f2tf32(vv4.y), f2tf32(vv4.z), f2tf32(vv4.w) };
            *(uint4*)(Vs + rr * AST + c4) = uv;
        }
        __syncthreads();

        // S = Q K^T  (8 n-tiles of kv, 8 k-steps of d)
        float s_[8][4];
#pragma unroll
        for (int nt = 0; nt < 8; nt++)
#pragma unroll
            for (int r = 0; r < 4; r++) s_[nt][r] = 0.f;

#pragma unroll
        for (int ks = 0; ks < 8; ks++) {
            const float* ap = Qs + (warp * 16 + gid) * AST + ks * 8 + qid;
            uint32_t a0 = ldb(ap), a1 = ldb(ap + 8 * AST), a2 = ldb(ap + 4),
                     a3 = ldb(ap + 8 * AST + 4);
#pragma unroll
            for (int nt = 0; nt < 8; nt++) {
                const float* bp = KsT + (ks * 8 + qid) * AST + nt * 8 + gid;
                mma_tf32(s_[nt], a0, a1, a2, a3, ldb(bp), ldb(bp + 4 * AST));
            }
        }

        // scale + mask + online softmax
        const bool diag = (kt >= ntiles - 2);
        float mloc[2] = { -1e30f, -1e30f };
#pragma unroll
        for (int nt = 0; nt < 8; nt++) {
            const int cbase = k0 + nt * 8 + 2 * qid;
#pragma unroll
            for (int r = 0; r < 4; r++) {
                float sv = s_[nt][r] * 0.125f;
                if (diag && (cbase + (r & 1) > row0 + 8 * (r >> 1))) sv = -1e30f;
                s_[nt][r] = sv;
                mloc[r >> 1] = fmaxf(mloc[r >> 1], sv);
            }
        }
#pragma unroll
        for (int r = 0; r < 2; r++) {
            mloc[r] = fmaxf(mloc[r], __shfl_xor_sync(0xffffffffu, mloc[r], 1));
            mloc[r] = fmaxf(mloc[r], __shfl_xor_sync(0xffffffffu, mloc[r], 2));
        }
        float alpha[2], sum[2];
#pragma unroll
        for (int r = 0; r < 2; r++) {
            const float mnew = fmaxf(m_[r], mloc[r]);
            alpha[r] = __expf(m_[r] - mnew);
            m_[r] = mnew;
            sum[r] = 0.f;
        }
#pragma unroll
        for (int nt = 0; nt < 8; nt++) {
#pragma unroll
            for (int r = 0; r < 4; r++) {
                float pv = __expf(s_[nt][r] - m_[r >> 1]);
                s_[nt][r] = pv;
                sum[r >> 1] += pv;
            }
            // store P (tf32 bits) for the PV mma
            float* pp = Ps + (warp * 16 + gid) * AST + nt * 8 + 2 * qid;
            *(float2*)pp = make_float2(__uint_as_float(f2tf32(s_[nt][0])),
                                       __uint_as_float(f2tf32(s_[nt][1])));
            *(float2*)(pp + 8 * AST) = make_float2(__uint_as_float(f2tf32(s_[nt][2])),
                                                   __uint_as_float(f2tf32(s_[nt][3])));
        }
#pragma unroll
        for (int r = 0; r < 2; r++) {
            sum[r] += __shfl_xor_sync(0xffffffffu, sum[r], 1);
            sum[r] += __shfl_xor_sync(0xffffffffu, sum[r], 2);
            l_[r] = l_[r] * alpha[r] + sum[r];
        }
#pragma unroll
        for (int nt = 0; nt < 8; nt++) {
            o_[nt][0] *= alpha[0]; o_[nt][1] *= alpha[0];
            o_[nt][2] *= alpha[1]; o_[nt][3] *= alpha[1];
        }
        __syncwarp();   // P visible to own warp's lanes

        // O += P V  (8 n-tiles of d, 8 k-steps of kv)
#pragma unroll
        for (int ks = 0; ks < 8; ks++) {
            const float* ap = Ps + (warp * 16 + gid) * AST + ks * 8 + qid;
            uint32_t a0 = ldb(ap), a1 = ldb(ap + 8 * AST), a2 = ldb(ap + 4),
                     a3 = ldb(ap + 8 * AST + 4);
#pragma unroll
            for (int nt = 0; nt < 8; nt++) {
                const float* bp = Vs + (ks * 8 + qid) * AST + nt * 8 + gid;
                mma_tf32(o_[nt], a0, a1, a2, a3, ldb(bp), ldb(bp + 4 * AST));
            }
        }
    }

    const float inv0 = 1.0f / l_[0];
    const float inv1 = 1.0f / l_[1];
    float* y0 = y + (size_t)(b * T_ + row0) * DIM_ + h * HD_;
    float* y1 = y0 + (size_t)8 * DIM_;
#pragma unroll
    for (int nt = 0; nt < 8; nt++) {
        const int cc = nt * 8 + 2 * qid;
        *(float2*)(y0 + cc) = make_float2(o_[nt][0] * inv0, o_[nt][1] * inv0);
        *(float2*)(y1 + cc) = make_float2(o_[nt][2] * inv1, o_[nt][3] * inv1);
    }
}

// ---------------------------------------------------------------------------
extern "C" void kernel_launch(void* const* d_in, const int* in_sizes, int n_in,
                              void* d_out, int out_size) {
    const float* x  = (const float*)d_in[0];
    const float* Wq = (const float*)d_in[1];
    const float* Wk = (const float*)d_in[2];
    const float* Wv = (const float*)d_in[3];
    const float* Wp = (const float*)d_in[4];
    float* out = (float*)d_out;

    float *pq, *pk, *pv, *py;
    cudaGetSymbolAddress((void**)&pq, g_q);
    cudaGetSymbolAddress((void**)&pk, g_k);
    cudaGetSymbolAddress((void**)&pv, g_v);
    cudaGetSymbolAddress((void**)&py, g_y);

    cudaFuncSetAttribute(gemm_mma, cudaFuncAttributeMaxDynamicSharedMemorySize, GEMM_SMEM);
    cudaFuncSetAttribute(attn_kernel, cudaFuncAttributeMaxDynamicSharedMemorySize, ATT_SMEM);

    dim3 gq(DIM_ / 128, BT_ / 128);    // (4, 128)
    dim3 gkv(KVD_ / 128, BT_ / 128);   // (2, 128)

    gemm_mma<<<gq, 256, GEMM_SMEM>>>(x, Wq, pq, BT_, DIM_, DIM_);
    gemm_mma<<<gkv, 256, GEMM_SMEM>>>(x, Wk, pk, BT_, KVD_, DIM_);
    gemm_mma<<<gkv, 256, GEMM_SMEM>>>(x, Wv, pv, BT_, KVD_, DIM_);

    rmsrope_kernel<<<dim3(BT_ / 8, NH_ + NKV_), 256>>>(pq, pk);

    attn_kernel<<<dim3(B_ * NH_, T_ / 128), 256, ATT_SMEM>>>(pq, pk, pv, py);

    gemm_mma<<<gq, 256, GEMM_SMEM>>>(py, Wp, out, BT_, DIM_, DIM_);
}

// round 5
// speedup vs baseline: 3.1045x; 1.0113x over previous
#include <cuda_runtime.h>
#include <math.h>
#include <stdint.h>

#define B_   8
#define T_   2048
#define DIM_ 512
#define NH_  8
#define NKV_ 4
#define HD_  64
#define KVD_ 256
#define BT_  (B_ * T_)

__device__ float g_q[BT_ * DIM_];
__device__ float g_k[BT_ * KVD_];
__device__ float g_v[BT_ * KVD_];
__device__ float g_y[BT_ * DIM_];
__device__ float2 g_rope[T_ * 32];     // (cos, sin) per (t, freq-lane)

// ---------------------------------------------------------------------------
// mma.sync m16n8k8 tf32 helpers
// ---------------------------------------------------------------------------
__device__ __forceinline__ uint32_t f2tf32(float x) {
    uint32_t r;
    asm("cvt.rna.tf32.f32 %0, %1;" : "=r"(r) : "f"(x));
    return r;
}
__device__ __forceinline__ void mma_tf32(float* c, uint32_t a0, uint32_t a1,
                                         uint32_t a2, uint32_t a3,
                                         uint32_t b0, uint32_t b1) {
    asm volatile(
        "mma.sync.aligned.m16n8k8.row.col.f32.tf32.tf32.f32 "
        "{%0,%1,%2,%3}, {%4,%5,%6,%7}, {%8,%9}, {%0,%1,%2,%3};"
        : "+f"(c[0]), "+f"(c[1]), "+f"(c[2]), "+f"(c[3])
        : "r"(a0), "r"(a1), "r"(a2), "r"(a3), "r"(b0), "r"(b1));
}
__device__ __forceinline__ uint32_t ldb(const float* p) {
    return __float_as_uint(*p);
}

// ---------------------------------------------------------------------------
// Tensor-core tf32 GEMM: C[M,N] = A[M,K] * B[N,K]^T.  CTA 128x128, K-chunk 32.
// ---------------------------------------------------------------------------
#define GST 36
#define GEMM_SMEM (4 * 128 * GST * 4)   // 73728 B

__global__ __launch_bounds__(256) void gemm_mma(const float* __restrict__ A,
                                                const float* __restrict__ Bm,
                                                float* __restrict__ C,
                                                int M, int N, int K) {
    extern __shared__ float sm[];
    const int tid  = threadIdx.x;
    const int warp = tid >> 5;
    const int lane = tid & 31;
    const int gid  = lane >> 2;
    const int qid  = lane & 3;
    const int bm = blockIdx.y << 7;
    const int bn = blockIdx.x << 7;
    const int wm = (warp >> 2) << 6;
    const int wn = (warp & 3) << 5;

    float acc[4][4][4];
#pragma unroll
    for (int mt = 0; mt < 4; mt++)
#pragma unroll
        for (int nt = 0; nt < 4; nt++)
#pragma unroll
            for (int r = 0; r < 4; r++) acc[mt][nt][r] = 0.f;

    const int nch = K >> 5;
    float4 ra[4], rb[4];

#pragma unroll
    for (int i = 0; i < 4; i++) {
        const int idx = (i << 8) + tid, row = idx >> 3, c4 = (idx & 7) << 2;
        ra[i] = *(const float4*)(A  + (size_t)(bm + row) * K + c4);
        rb[i] = *(const float4*)(Bm + (size_t)(bn + row) * K + c4);
    }
    {
        float* As = sm; float* Bs = sm + 128 * GST;
#pragma unroll
        for (int i = 0; i < 4; i++) {
            const int idx = (i << 8) + tid, row = idx >> 3, c4 = (idx & 7) << 2;
            uint4 ua = { f2tf32(ra[i].x), f2tf32(ra[i].y), f2tf32(ra[i].z), f2tf32(ra[i].w) };
            uint4 ub = { f2tf32(rb[i].x), f2tf32(rb[i].y), f2tf32(rb[i].z), f2tf32(rb[i].w) };
            *(uint4*)(As + row * GST + c4) = ua;
            *(uint4*)(Bs + row * GST + c4) = ub;
        }
    }
    __syncthreads();

    for (int kc = 0; kc < nch; kc++) {
        if (kc + 1 < nch) {
            const int k0 = (kc + 1) << 5;
#pragma unroll
            for (int i = 0; i < 4; i++) {
                const int idx = (i << 8) + tid, row = idx >> 3, c4 = (idx & 7) << 2;
                ra[i] = *(const float4*)(A  + (size_t)(bm + row) * K + k0 + c4);
                rb[i] = *(const float4*)(Bm + (size_t)(bn + row) * K + k0 + c4);
            }
        }
        {
            const float* As = sm + (kc & 1) * (2 * 128 * GST);
            const float* Bs = As + 128 * GST;
#pragma unroll
            for (int ks = 0; ks < 4; ks++) {
                uint32_t af[4][4], bf[4][2];
#pragma unroll
                for (int mt = 0; mt < 4; mt++) {
                    const float* ap = As + (wm + mt * 16 + gid) * GST + ks * 8 + qid;
                    af[mt][0] = ldb(ap);
                    af[mt][1] = ldb(ap + 8 * GST);
                    af[mt][2] = ldb(ap + 4);
                    af[mt][3] = ldb(ap + 8 * GST + 4);
                }
#pragma unroll
                for (int nt = 0; nt < 4; nt++) {
                    const float* bp = Bs + (wn + nt * 8 + gid) * GST + ks * 8 + qid;
                    bf[nt][0] = ldb(bp);
                    bf[nt][1] = ldb(bp + 4);
                }
#pragma unroll
                for (int mt = 0; mt < 4; mt++)
#pragma unroll
                    for (int nt = 0; nt < 4; nt++)
                        mma_tf32(acc[mt][nt], af[mt][0], af[mt][1], af[mt][2], af[mt][3],
                                 bf[nt][0], bf[nt][1]);
            }
        }
        if (kc + 1 < nch) {
            __syncthreads();
            float* As = sm + ((kc + 1) & 1) * (2 * 128 * GST);
            float* Bs = As + 128 * GST;
#pragma unroll
            for (int i = 0; i < 4; i++) {
                const int idx = (i << 8) + tid, row = idx >> 3, c4 = (idx & 7) << 2;
                uint4 ua = { f2tf32(ra[i].x), f2tf32(ra[i].y), f2tf32(ra[i].z), f2tf32(ra[i].w) };
                uint4 ub = { f2tf32(rb[i].x), f2tf32(rb[i].y), f2tf32(rb[i].z), f2tf32(rb[i].w) };
                *(uint4*)(As + row * GST + c4) = ua;
                *(uint4*)(Bs + row * GST + c4) = ub;
            }
            __syncthreads();
        }
    }

#pragma unroll
    for (int mt = 0; mt < 4; mt++) {
        const int r0 = bm + wm + mt * 16 + gid;
#pragma unroll
        for (int nt = 0; nt < 4; nt++) {
            const int cc = bn + wn + nt * 8 + 2 * qid;
            *(float2*)(C + (size_t)r0 * N + cc)       = make_float2(acc[mt][nt][0], acc[mt][nt][1]);
            *(float2*)(C + (size_t)(r0 + 8) * N + cc) = make_float2(acc[mt][nt][2], acc[mt][nt][3]);
        }
    }
}

// ---------------------------------------------------------------------------
// RoPE table + RMSNorm/RoPE apply
// ---------------------------------------------------------------------------
__constant__ float c_invfreq[32] = {
    1.0f, 0.7498942093324559f, 0.5623413251903491f, 0.4216965034285822f,
    0.31622776601683794f, 0.23713737056616552f, 0.1778279410038923f, 0.13335214321633242f,
    0.1f, 0.07498942093324558f, 0.05623413251903491f, 0.04216965034285822f,
    0.031622776601683794f, 0.023713737056616554f, 0.01778279410038923f, 0.013335214321633242f,
    0.01f, 0.007498942093324559f, 0.005623413251903491f, 0.004216965034285823f,
    0.0031622776601683794f, 0.0023713737056616554f, 0.001778279410038923f, 0.0013335214321633242f,
    0.001f, 0.0007498942093324558f, 0.0005623413251903491f, 0.0004216965034285822f,
    0.00031622776601683794f, 0.00023713737056616552f, 0.0001778279410038923f, 0.00013335214321633242f
};

__global__ __launch_bounds__(256) void rope_table_kernel() {
    const int idx = blockIdx.x * 256 + threadIdx.x;   // T_*32 total
    const int t = idx >> 5, lane = idx & 31;
    float s, c;
    sincosf((float)t * c_invfreq[lane], &s, &c);
    g_rope[idx] = make_float2(c, s);
}

__global__ __launch_bounds__(256) void rmsrope_kernel(float* __restrict__ q,
                                                      float* __restrict__ k) {
    const int lane = threadIdx.x & 31;
    const int token = (blockIdx.x << 3) + (threadIdx.x >> 5);
    const int head = blockIdx.y;
    const int t = token & (T_ - 1);

    float* base = (head < NH_)
        ? q + (size_t)token * DIM_ + head * HD_
        : k + (size_t)token * KVD_ + (head - NH_) * HD_;

    float x1 = base[lane];
    float x2 = base[lane + 32];
    float ss = x1 * x1 + x2 * x2;
#pragma unroll
    for (int o = 16; o; o >>= 1) ss += __shfl_xor_sync(0xffffffffu, ss, o);
    const float r = rsqrtf(ss * (1.0f / 64.0f) + 1.1920928955078125e-07f);
    x1 *= r; x2 *= r;

    const float2 cs = g_rope[t * 32 + lane];
    base[lane]      =  x1 * cs.x + x2 * cs.y;
    base[lane + 32] = -x1 * cs.y + x2 * cs.x;
}

// ---------------------------------------------------------------------------
// Flash attention, tf32 mma. 256 threads, q-tile 128, kv-tile 64.
// Register-prefetch of next K/V tile overlaps LDG latency with mma/softmax.
// ---------------------------------------------------------------------------
#define AST 68
#define ATT_SMEM ((128 + 64 + 64 + 128) * AST * 4)   // 104448 B

__global__ __launch_bounds__(256) void attn_kernel(const float* __restrict__ q,
                                                   const float* __restrict__ k,
                                                   const float* __restrict__ v,
                                                   float* __restrict__ y) {
    extern __shared__ float sm[];
    float* Qs  = sm;                       // [128][AST]
    float* KsT = Qs + 128 * AST;           // [64 d][AST kv]
    float* Vs  = KsT + 64 * AST;           // [64 kv][AST d]
    float* Ps  = Vs + 64 * AST;            // [128][AST kv]

    const int tid  = threadIdx.x;
    const int warp = tid >> 5;
    const int lane = tid & 31;
    const int gid  = lane >> 2;
    const int qid  = lane & 3;
    const int bh = blockIdx.x;
    const int b  = bh >> 3;
    const int h  = bh & 7;
    const int hk = h >> 1;
    const int q0 = blockIdx.y << 7;

    const float* qb = q + ((size_t)(b * T_ + q0)) * DIM_ + h * HD_;
    const float* kb = k + ((size_t)(b * T_)) * KVD_ + hk * HD_;
    const float* vb = v + ((size_t)(b * T_)) * KVD_ + hk * HD_;

    // Q tile (tf32 bits)
#pragma unroll
    for (int i = 0; i < 8; i++) {
        const int idx = (i << 8) + tid;
        const int rr = idx >> 4, c4 = (idx & 15) << 2;
        float4 vq = *(const float4*)(qb + (size_t)rr * DIM_ + c4);
        uint4 uq = { f2tf32(vq.x), f2tf32(vq.y), f2tf32(vq.z), f2tf32(vq.w) };
        *(uint4*)(Qs + rr * AST + c4) = uq;
    }

    const int row0 = q0 + warp * 16 + gid;
    float m_[2], l_[2], o_[8][4];
    m_[0] = m_[1] = -1e30f;
    l_[0] = l_[1] = 0.f;
#pragma unroll
    for (int nt = 0; nt < 8; nt++)
#pragma unroll
        for (int r = 0; r < 4; r++) o_[nt][r] = 0.f;

    const int ntiles = 2 * (blockIdx.y + 1);
    float4 rk[4], rv[4];

    // prefetch kv-tile 0
#pragma unroll
    for (int i = 0; i < 4; i++) {
        const int idx = (i << 8) + tid;
        const int rr = idx >> 4, c4 = (idx & 15) << 2;
        rk[i] = *(const float4*)(kb + (size_t)rr * KVD_ + c4);
        rv[i] = *(const float4*)(vb + (size_t)rr * KVD_ + c4);
    }

    for (int kt = 0; kt < ntiles; kt++) {
        const int k0 = kt << 6;
        __syncthreads();   // prior PV reads done; Q tile done (iter 0)
        // store prefetched tile (tf32 bits; K transposed)
#pragma unroll
        for (int i = 0; i < 4; i++) {
            const int idx = (i << 8) + tid;
            const int rr = idx >> 4, c4 = (idx & 15) << 2;
            KsT[(c4 + 0) * AST + rr] = __uint_as_float(f2tf32(rk[i].x));
            KsT[(c4 + 1) * AST + rr] = __uint_as_float(f2tf32(rk[i].y));
            KsT[(c4 + 2) * AST + rr] = __uint_as_float(f2tf32(rk[i].z));
            KsT[(c4 + 3) * AST + rr] = __uint_as_float(f2tf32(rk[i].w));
            uint4 uv = { f2tf32(rv[i].x), f2tf32(rv[i].y), f2tf32(rv[i].z), f2tf32(rv[i].w) };
            *(uint4*)(Vs + rr * AST + c4) = uv;
        }
        __syncthreads();

        // prefetch next tile — overlaps all the compute below
        if (kt + 1 < ntiles) {
            const int kn = (kt + 1) << 6;
#pragma unroll
            for (int i = 0; i < 4; i++) {
                const int idx = (i << 8) + tid;
                const int rr = idx >> 4, c4 = (idx & 15) << 2;
                rk[i] = *(const float4*)(kb + (size_t)(kn + rr) * KVD_ + c4);
                rv[i] = *(const float4*)(vb + (size_t)(kn + rr) * KVD_ + c4);
            }
        }

        // S = Q K^T
        float s_[8][4];
#pragma unroll
        for (int nt = 0; nt < 8; nt++)
#pragma unroll
            for (int r = 0; r < 4; r++) s_[nt][r] = 0.f;

#pragma unroll
        for (int ks = 0; ks < 8; ks++) {
            const float* ap = Qs + (warp * 16 + gid) * AST + ks * 8 + qid;
            uint32_t a0 = ldb(ap), a1 = ldb(ap + 8 * AST), a2 = ldb(ap + 4),
                     a3 = ldb(ap + 8 * AST + 4);
#pragma unroll
            for (int nt = 0; nt < 8; nt++) {
                const float* bp = KsT + (ks * 8 + qid) * AST + nt * 8 + gid;
                mma_tf32(s_[nt], a0, a1, a2, a3, ldb(bp), ldb(bp + 4 * AST));
            }
        }

        // scale + mask + online softmax
        const bool diag = (kt >= ntiles - 2);
        float mloc[2] = { -1e30f, -1e30f };
#pragma unroll
        for (int nt = 0; nt < 8; nt++) {
            const int cbase = k0 + nt * 8 + 2 * qid;
#pragma unroll
            for (int r = 0; r < 4; r++) {
                float sv = s_[nt][r] * 0.125f;
                if (diag && (cbase + (r & 1) > row0 + 8 * (r >> 1))) sv = -1e30f;
                s_[nt][r] = sv;
                mloc[r >> 1] = fmaxf(mloc[r >> 1], sv);
            }
        }
#pragma unroll
        for (int r = 0; r < 2; r++) {
            mloc[r] = fmaxf(mloc[r], __shfl_xor_sync(0xffffffffu, mloc[r], 1));
            mloc[r] = fmaxf(mloc[r], __shfl_xor_sync(0xffffffffu, mloc[r], 2));
        }
        float alpha[2], sum[2];
#pragma unroll
        for (int r = 0; r < 2; r++) {
            const float mnew = fmaxf(m_[r], mloc[r]);
            alpha[r] = __expf(m_[r] - mnew);
            m_[r] = mnew;
            sum[r] = 0.f;
        }
#pragma unroll
        for (int nt = 0; nt < 8; nt++) {
#pragma unroll
            for (int r = 0; r < 4; r++) {
                float pv = __expf(s_[nt][r] - m_[r >> 1]);
                s_[nt][r] = pv;
                sum[r >> 1] += pv;
            }
            float* pp = Ps + (warp * 16 + gid) * AST + nt * 8 + 2 * qid;
            *(float2*)pp = make_float2(__uint_as_float(f2tf32(s_[nt][0])),
                                       __uint_as_float(f2tf32(s_[nt][1])));
            *(float2*)(pp + 8 * AST) = make_float2(__uint_as_float(f2tf32(s_[nt][2])),
                                                   __uint_as_float(f2tf32(s_[nt][3])));
        }
#pragma unroll
        for (int r = 0; r < 2; r++) {
            sum[r] += __shfl_xor_sync(0xffffffffu, sum[r], 1);
            sum[r] += __shfl_xor_sync(0xffffffffu, sum[r], 2);
            l_[r] = l_[r] * alpha[r] + sum[r];
        }
#pragma unroll
        for (int nt = 0; nt < 8; nt++) {
            o_[nt][0] *= alpha[0]; o_[nt][1] *= alpha[0];
            o_[nt][2] *= alpha[1]; o_[nt][3] *= alpha[1];
        }
        __syncwarp();

        // O += P V
#pragma unroll
        for (int ks = 0; ks < 8; ks++) {
            const float* ap = Ps + (warp * 16 + gid) * AST + ks * 8 + qid;
            uint32_t a0 = ldb(ap), a1 = ldb(ap + 8 * AST), a2 = ldb(ap + 4),
                     a3 = ldb(ap + 8 * AST + 4);
#pragma unroll
            for (int nt = 0; nt < 8; nt++) {
                const float* bp = Vs + (ks * 8 + qid) * AST + nt * 8 + gid;
                mma_tf32(o_[nt], a0, a1, a2, a3, ldb(bp), ldb(bp + 4 * AST));
            }
        }
    }

    const float inv0 = 1.0f / l_[0];
    const float inv1 = 1.0f / l_[1];
    float* y0 = y + (size_t)(b * T_ + row0) * DIM_ + h * HD_;
    float* y1 = y0 + (size_t)8 * DIM_;
#pragma unroll
    for (int nt = 0; nt < 8; nt++) {
        const int cc = nt * 8 + 2 * qid;
        *(float2*)(y0 + cc) = make_float2(o_[nt][0] * inv0, o_[nt][1] * inv0);
        *(float2*)(y1 + cc) = make_float2(o_[nt][2] * inv1, o_[nt][3] * inv1);
    }
}

// ---------------------------------------------------------------------------
extern "C" void kernel_launch(void* const* d_in, const int* in_sizes, int n_in,
                              void* d_out, int out_size) {
    const float* x  = (const float*)d_in[0];
    const float* Wq = (const float*)d_in[1];
    const float* Wk = (const float*)d_in[2];
    const float* Wv = (const float*)d_in[3];
    const float* Wp = (const float*)d_in[4];
    float* out = (float*)d_out;

    float *pq, *pk, *pv, *py;
    cudaGetSymbolAddress((void**)&pq, g_q);
    cudaGetSymbolAddress((void**)&pk, g_k);
    cudaGetSymbolAddress((void**)&pv, g_v);
    cudaGetSymbolAddress((void**)&py, g_y);

    cudaFuncSetAttribute(gemm_mma, cudaFuncAttributeMaxDynamicSharedMemorySize, GEMM_SMEM);
    cudaFuncSetAttribute(attn_kernel, cudaFuncAttributeMaxDynamicSharedMemorySize, ATT_SMEM);

    dim3 gq(DIM_ / 128, BT_ / 128);
    dim3 gkv(KVD_ / 128, BT_ / 128);

    rope_table_kernel<<<T_ * 32 / 256, 256>>>();

    gemm_mma<<<gq, 256, GEMM_SMEM>>>(x, Wq, pq, BT_, DIM_, DIM_);
    gemm_mma<<<gkv, 256, GEMM_SMEM>>>(x, Wk, pk, BT_, KVD_, DIM_);
    gemm_mma<<<gkv, 256, GEMM_SMEM>>>(x, Wv, pv, BT_, KVD_, DIM_);

    rmsrope_kernel<<<dim3(BT_ / 8, NH_ + NKV_), 256>>>(pq, pk);

    attn_kernel<<<dim3(B_ * NH_, T_ / 128), 256, ATT_SMEM>>>(pq, pk, pv, py);

    gemm_mma<<<gq, 256, GEMM_SMEM>>>(py, Wp, out, BT_, DIM_, DIM_);
}

// round 6
// speedup vs baseline: 3.2378x; 1.0429x over previous
#include <cuda_runtime.h>
#include <math.h>
#include <stdint.h>

#define B_   8
#define T_   2048
#define DIM_ 512
#define NH_  8
#define NKV_ 4
#define HD_  64
#define KVD_ 256
#define BT_  (B_ * T_)

__device__ float g_q[BT_ * DIM_];
__device__ float g_k[BT_ * KVD_];
__device__ float g_v[BT_ * KVD_];
__device__ float g_y[BT_ * DIM_];
__device__ float2 g_rope[T_ * 32];     // (cos, sin) per (t, freq-lane)

// ---------------------------------------------------------------------------
// mma.sync m16n8k8 tf32 helpers
// ---------------------------------------------------------------------------
__device__ __forceinline__ uint32_t f2tf32(float x) {
    uint32_t r;
    asm("cvt.rna.tf32.f32 %0, %1;" : "=r"(r) : "f"(x));
    return r;
}
__device__ __forceinline__ float ex2f(float x) {
    float r;
    asm("ex2.approx.ftz.f32 %0, %1;" : "=f"(r) : "f"(x));
    return r;
}
__device__ __forceinline__ void mma_tf32(float* c, uint32_t a0, uint32_t a1,
                                         uint32_t a2, uint32_t a3,
                                         uint32_t b0, uint32_t b1) {
    asm volatile(
        "mma.sync.aligned.m16n8k8.row.col.f32.tf32.tf32.f32 "
        "{%0,%1,%2,%3}, {%4,%5,%6,%7}, {%8,%9}, {%0,%1,%2,%3};"
        : "+f"(c[0]), "+f"(c[1]), "+f"(c[2]), "+f"(c[3])
        : "r"(a0), "r"(a1), "r"(a2), "r"(a3), "r"(b0), "r"(b1));
}
__device__ __forceinline__ uint32_t ldb(const float* p) {
    return __float_as_uint(*p);
}

// ---------------------------------------------------------------------------
// Tensor-core tf32 GEMM: C[M,N] = A[M,K] * B[N,K]^T.  CTA 128x128, K-chunk 32.
// ---------------------------------------------------------------------------
#define GST 36
#define GEMM_SMEM (4 * 128 * GST * 4)   // 73728 B

__global__ __launch_bounds__(256) void gemm_mma(const float* __restrict__ A,
                                                const float* __restrict__ Bm,
                                                float* __restrict__ C,
                                                int M, int N, int K) {
    extern __shared__ float sm[];
    const int tid  = threadIdx.x;
    const int warp = tid >> 5;
    const int lane = tid & 31;
    const int gid  = lane >> 2;
    const int qid  = lane & 3;
    const int bm = blockIdx.y << 7;
    const int bn = blockIdx.x << 7;
    const int wm = (warp >> 2) << 6;
    const int wn = (warp & 3) << 5;

    float acc[4][4][4];
#pragma unroll
    for (int mt = 0; mt < 4; mt++)
#pragma unroll
        for (int nt = 0; nt < 4; nt++)
#pragma unroll
            for (int r = 0; r < 4; r++) acc[mt][nt][r] = 0.f;

    const int nch = K >> 5;
    float4 ra[4], rb[4];

#pragma unroll
    for (int i = 0; i < 4; i++) {
        const int idx = (i << 8) + tid, row = idx >> 3, c4 = (idx & 7) << 2;
        ra[i] = *(const float4*)(A  + (size_t)(bm + row) * K + c4);
        rb[i] = *(const float4*)(Bm + (size_t)(bn + row) * K + c4);
    }
    {
        float* As = sm; float* Bs = sm + 128 * GST;
#pragma unroll
        for (int i = 0; i < 4; i++) {
            const int idx = (i << 8) + tid, row = idx >> 3, c4 = (idx & 7) << 2;
            uint4 ua = { f2tf32(ra[i].x), f2tf32(ra[i].y), f2tf32(ra[i].z), f2tf32(ra[i].w) };
            uint4 ub = { f2tf32(rb[i].x), f2tf32(rb[i].y), f2tf32(rb[i].z), f2tf32(rb[i].w) };
            *(uint4*)(As + row * GST + c4) = ua;
            *(uint4*)(Bs + row * GST + c4) = ub;
        }
    }
    __syncthreads();

    for (int kc = 0; kc < nch; kc++) {
        if (kc + 1 < nch) {
            const int k0 = (kc + 1) << 5;
#pragma unroll
            for (int i = 0; i < 4; i++) {
                const int idx = (i << 8) + tid, row = idx >> 3, c4 = (idx & 7) << 2;
                ra[i] = *(const float4*)(A  + (size_t)(bm + row) * K + k0 + c4);
                rb[i] = *(const float4*)(Bm + (size_t)(bn + row) * K + k0 + c4);
            }
        }
        {
            const float* As = sm + (kc & 1) * (2 * 128 * GST);
            const float* Bs = As + 128 * GST;
#pragma unroll
            for (int ks = 0; ks < 4; ks++) {
                uint32_t af[4][4], bf[4][2];
#pragma unroll
                for (int mt = 0; mt < 4; mt++) {
                    const float* ap = As + (wm + mt * 16 + gid) * GST + ks * 8 + qid;
                    af[mt][0] = ldb(ap);
                    af[mt][1] = ldb(ap + 8 * GST);
                    af[mt][2] = ldb(ap + 4);
                    af[mt][3] = ldb(ap + 8 * GST + 4);
                }
#pragma unroll
                for (int nt = 0; nt < 4; nt++) {
                    const float* bp = Bs + (wn + nt * 8 + gid) * GST + ks * 8 + qid;
                    bf[nt][0] = ldb(bp);
                    bf[nt][1] = ldb(bp + 4);
                }
#pragma unroll
                for (int mt = 0; mt < 4; mt++)
#pragma unroll
                    for (int nt = 0; nt < 4; nt++)
                        mma_tf32(acc[mt][nt], af[mt][0], af[mt][1], af[mt][2], af[mt][3],
                                 bf[nt][0], bf[nt][1]);
            }
        }
        if (kc + 1 < nch) {
            __syncthreads();
            float* As = sm + ((kc + 1) & 1) * (2 * 128 * GST);
            float* Bs = As + 128 * GST;
#pragma unroll
            for (int i = 0; i < 4; i++) {
                const int idx = (i << 8) + tid, row = idx >> 3, c4 = (idx & 7) << 2;
                uint4 ua = { f2tf32(ra[i].x), f2tf32(ra[i].y), f2tf32(ra[i].z), f2tf32(ra[i].w) };
                uint4 ub = { f2tf32(rb[i].x), f2tf32(rb[i].y), f2tf32(rb[i].z), f2tf32(rb[i].w) };
                *(uint4*)(As + row * GST + c4) = ua;
                *(uint4*)(Bs + row * GST + c4) = ub;
            }
            __syncthreads();
        }
    }

#pragma unroll
    for (int mt = 0; mt < 4; mt++) {
        const int r0 = bm + wm + mt * 16 + gid;
#pragma unroll
        for (int nt = 0; nt < 4; nt++) {
            const int cc = bn + wn + nt * 8 + 2 * qid;
            *(float2*)(C + (size_t)r0 * N + cc)       = make_float2(acc[mt][nt][0], acc[mt][nt][1]);
            *(float2*)(C + (size_t)(r0 + 8) * N + cc) = make_float2(acc[mt][nt][2], acc[mt][nt][3]);
        }
    }
}

// ---------------------------------------------------------------------------
// RoPE table + RMSNorm/RoPE apply
// ---------------------------------------------------------------------------
__constant__ float c_invfreq[32] = {
    1.0f, 0.7498942093324559f, 0.5623413251903491f, 0.4216965034285822f,
    0.31622776601683794f, 0.23713737056616552f, 0.1778279410038923f, 0.13335214321633242f,
    0.1f, 0.07498942093324558f, 0.05623413251903491f, 0.04216965034285822f,
    0.031622776601683794f, 0.023713737056616554f, 0.01778279410038923f, 0.013335214321633242f,
    0.01f, 0.007498942093324559f, 0.005623413251903491f, 0.004216965034285823f,
    0.0031622776601683794f, 0.0023713737056616554f, 0.001778279410038923f, 0.0013335214321633242f,
    0.001f, 0.0007498942093324558f, 0.0005623413251903491f, 0.0004216965034285822f,
    0.00031622776601683794f, 0.00023713737056616552f, 0.0001778279410038923f, 0.00013335214321633242f
};

__global__ __launch_bounds__(256) void rope_table_kernel() {
    const int idx = blockIdx.x * 256 + threadIdx.x;
    const int t = idx >> 5, lane = idx & 31;
    float s, c;
    sincosf((float)t * c_invfreq[lane], &s, &c);
    g_rope[idx] = make_float2(c, s);
}

__global__ __launch_bounds__(256) void rmsrope_kernel(float* __restrict__ q,
                                                      float* __restrict__ k) {
    const int lane = threadIdx.x & 31;
    const int token = (blockIdx.x << 3) + (threadIdx.x >> 5);
    const int head = blockIdx.y;
    const int t = token & (T_ - 1);

    float* base = (head < NH_)
        ? q + (size_t)token * DIM_ + head * HD_
        : k + (size_t)token * KVD_ + (head - NH_) * HD_;

    float x1 = base[lane];
    float x2 = base[lane + 32];
    float ss = x1 * x1 + x2 * x2;
#pragma unroll
    for (int o = 16; o; o >>= 1) ss += __shfl_xor_sync(0xffffffffu, ss, o);
    const float r = rsqrtf(ss * (1.0f / 64.0f) + 1.1920928955078125e-07f);
    x1 *= r; x2 *= r;

    const float2 cs = g_rope[t * 32 + lane];
    base[lane]      =  x1 * cs.x + x2 * cs.y;
    base[lane + 32] = -x1 * cs.y + x2 * cs.x;
}

// ---------------------------------------------------------------------------
// Flash attention, tf32 mma. 256 threads, q-tile 128, kv-tile 64.
// __launch_bounds__(256,2): cap 128 regs -> 2 CTAs/SM (16 warps) for latency
// hiding. Softmax in base-2 (scale folded with log2e; single EX2 per element).
// ---------------------------------------------------------------------------
#define AST 68
#define ATT_SMEM ((128 + 64 + 64 + 128) * AST * 4)   // 104448 B
#define SCALE2 0.18033688011112042f   // 0.125 * log2(e)

__global__ __launch_bounds__(256, 2) void attn_kernel(const float* __restrict__ q,
                                                      const float* __restrict__ k,
                                                      const float* __restrict__ v,
                                                      float* __restrict__ y) {
    extern __shared__ float sm[];
    float* Qs  = sm;                       // [128][AST]
    float* KsT = Qs + 128 * AST;           // [64 d][AST kv]
    float* Vs  = KsT + 64 * AST;           // [64 kv][AST d]
    float* Ps  = Vs + 64 * AST;            // [128][AST kv]

    const int tid  = threadIdx.x;
    const int warp = tid >> 5;
    const int lane = tid & 31;
    const int gid  = lane >> 2;
    const int qid  = lane & 3;
    const int bh = blockIdx.x;
    const int b  = bh >> 3;
    const int h  = bh & 7;
    const int hk = h >> 1;
    const int q0 = blockIdx.y << 7;

    const float* qb = q + ((size_t)(b * T_ + q0)) * DIM_ + h * HD_;
    const float* kb = k + ((size_t)(b * T_)) * KVD_ + hk * HD_;
    const float* vb = v + ((size_t)(b * T_)) * KVD_ + hk * HD_;

    // Q tile (tf32 bits)
#pragma unroll
    for (int i = 0; i < 8; i++) {
        const int idx = (i << 8) + tid;
        const int rr = idx >> 4, c4 = (idx & 15) << 2;
        float4 vq = *(const float4*)(qb + (size_t)rr * DIM_ + c4);
        uint4 uq = { f2tf32(vq.x), f2tf32(vq.y), f2tf32(vq.z), f2tf32(vq.w) };
        *(uint4*)(Qs + rr * AST + c4) = uq;
    }

    const int row0 = q0 + warp * 16 + gid;
    float m_[2], l_[2], o_[8][4];
    m_[0] = m_[1] = -1e30f;
    l_[0] = l_[1] = 0.f;
#pragma unroll
    for (int nt = 0; nt < 8; nt++)
#pragma unroll
        for (int r = 0; r < 4; r++) o_[nt][r] = 0.f;

    const int ntiles = 2 * (blockIdx.y + 1);
    for (int kt = 0; kt < ntiles; kt++) {
        const int k0 = kt << 6;
        __syncthreads();   // prior PV reads done; Q tile done (iter 0)
#pragma unroll
        for (int i = 0; i < 4; i++) {
            const int idx = (i << 8) + tid;
            const int rr = idx >> 4, c4 = (idx & 15) << 2;
            float4 kk4 = *(const float4*)(kb + (size_t)(k0 + rr) * KVD_ + c4);
            KsT[(c4 + 0) * AST + rr] = __uint_as_float(f2tf32(kk4.x));
            KsT[(c4 + 1) * AST + rr] = __uint_as_float(f2tf32(kk4.y));
            KsT[(c4 + 2) * AST + rr] = __uint_as_float(f2tf32(kk4.z));
            KsT[(c4 + 3) * AST + rr] = __uint_as_float(f2tf32(kk4.w));
            float4 vv4 = *(const float4*)(vb + (size_t)(k0 + rr) * KVD_ + c4);
            uint4 uv = { f2tf32(vv4.x), f2tf32(vv4.y), f2tf32(vv4.z), f2tf32(vv4.w) };
            *(uint4*)(Vs + rr * AST + c4) = uv;
        }
        __syncthreads();

        // S = Q K^T
        float s_[8][4];
#pragma unroll
        for (int nt = 0; nt < 8; nt++)
#pragma unroll
            for (int r = 0; r < 4; r++) s_[nt][r] = 0.f;

#pragma unroll
        for (int ks = 0; ks < 8; ks++) {
            const float* ap = Qs + (warp * 16 + gid) * AST + ks * 8 + qid;
            uint32_t a0 = ldb(ap), a1 = ldb(ap + 8 * AST), a2 = ldb(ap + 4),
                     a3 = ldb(ap + 8 * AST + 4);
#pragma unroll
            for (int nt = 0; nt < 8; nt++) {
                const float* bp = KsT + (ks * 8 + qid) * AST + nt * 8 + gid;
                mma_tf32(s_[nt], a0, a1, a2, a3, ldb(bp), ldb(bp + 4 * AST));
            }
        }

        // scale (base-2) + mask + online softmax
        const bool diag = (kt >= ntiles - 2);
        float mloc[2] = { -1e30f, -1e30f };
#pragma unroll
        for (int nt = 0; nt < 8; nt++) {
            const int cbase = k0 + nt * 8 + 2 * qid;
#pragma unroll
            for (int r = 0; r < 4; r++) {
                float sv = s_[nt][r] * SCALE2;
                if (diag && (cbase + (r & 1) > row0 + 8 * (r >> 1))) sv = -1e30f;
                s_[nt][r] = sv;
                mloc[r >> 1] = fmaxf(mloc[r >> 1], sv);
            }
        }
#pragma unroll
        for (int r = 0; r < 2; r++) {
            mloc[r] = fmaxf(mloc[r], __shfl_xor_sync(0xffffffffu, mloc[r], 1));
            mloc[r] = fmaxf(mloc[r], __shfl_xor_sync(0xffffffffu, mloc[r], 2));
        }
        float alpha[2], sum[2];
#pragma unroll
        for (int r = 0; r < 2; r++) {
            const float mnew = fmaxf(m_[r], mloc[r]);
            alpha[r] = ex2f(m_[r] - mnew);
            m_[r] = mnew;
            sum[r] = 0.f;
        }
#pragma unroll
        for (int nt = 0; nt < 8; nt++) {
#pragma unroll
            for (int r = 0; r < 4; r++) {
                float pv = ex2f(s_[nt][r] - m_[r >> 1]);
                s_[nt][r] = pv;
                sum[r >> 1] += pv;
            }
            float* pp = Ps + (warp * 16 + gid) * AST + nt * 8 + 2 * qid;
            *(float2*)pp = make_float2(__uint_as_float(f2tf32(s_[nt][0])),
                                       __uint_as_float(f2tf32(s_[nt][1])));
            *(float2*)(pp + 8 * AST) = make_float2(__uint_as_float(f2tf32(s_[nt][2])),
                                                   __uint_as_float(f2tf32(s_[nt][3])));
        }
#pragma unroll
        for (int r = 0; r < 2; r++) {
            sum[r] += __shfl_xor_sync(0xffffffffu, sum[r], 1);
            sum[r] += __shfl_xor_sync(0xffffffffu, sum[r], 2);
            l_[r] = l_[r] * alpha[r] + sum[r];
        }
#pragma unroll
        for (int nt = 0; nt < 8; nt++) {
            o_[nt][0] *= alpha[0]; o_[nt][1] *= alpha[0];
            o_[nt][2] *= alpha[1]; o_[nt][3] *= alpha[1];
        }
        __syncwarp();

        // O += P V
#pragma unroll
        for (int ks = 0; ks < 8; ks++) {
            const float* ap = Ps + (warp * 16 + gid) * AST + ks * 8 + qid;
            uint32_t a0 = ldb(ap), a1 = ldb(ap + 8 * AST), a2 = ldb(ap + 4),
                     a3 = ldb(ap + 8 * AST + 4);
#pragma unroll
            for (int nt = 0; nt < 8; nt++) {
                const float* bp = Vs + (ks * 8 + qid) * AST + nt * 8 + gid;
                mma_tf32(o_[nt], a0, a1, a2, a3, ldb(bp), ldb(bp + 4 * AST));
            }
        }
    }

    const float inv0 = 1.0f / l_[0];
    const float inv1 = 1.0f / l_[1];
    float* y0 = y + (size_t)(b * T_ + row0) * DIM_ + h * HD_;
    float* y1 = y0 + (size_t)8 * DIM_;
#pragma unroll
    for (int nt = 0; nt < 8; nt++) {
        const int cc = nt * 8 + 2 * qid;
        *(float2*)(y0 + cc) = make_float2(o_[nt][0] * inv0, o_[nt][1] * inv0);
        *(float2*)(y1 + cc) = make_float2(o_[nt][2] * inv1, o_[nt][3] * inv1);
    }
}

// ---------------------------------------------------------------------------
extern "C" void kernel_launch(void* const* d_in, const int* in_sizes, int n_in,
                              void* d_out, int out_size) {
    const float* x  = (const float*)d_in[0];
    const float* Wq = (const float*)d_in[1];
    const float* Wk = (const float*)d_in[2];
    const float* Wv = (const float*)d_in[3];
    const float* Wp = (const float*)d_in[4];
    float* out = (float*)d_out;

    float *pq, *pk, *pv, *py;
    cudaGetSymbolAddress((void**)&pq, g_q);
    cudaGetSymbolAddress((void**)&pk, g_k);
    cudaGetSymbolAddress((void**)&pv, g_v);
    cudaGetSymbolAddress((void**)&py, g_y);

    cudaFuncSetAttribute(gemm_mma, cudaFuncAttributeMaxDynamicSharedMemorySize, GEMM_SMEM);
    cudaFuncSetAttribute(attn_kernel, cudaFuncAttributeMaxDynamicSharedMemorySize, ATT_SMEM);

    dim3 gq(DIM_ / 128, BT_ / 128);
    dim3 gkv(KVD_ / 128, BT_ / 128);

    rope_table_kernel<<<T_ * 32 / 256, 256>>>();

    gemm_mma<<<gq, 256, GEMM_SMEM>>>(x, Wq, pq, BT_, DIM_, DIM_);
    gemm_mma<<<gkv, 256, GEMM_SMEM>>>(x, Wk, pk, BT_, KVD_, DIM_);
    gemm_mma<<<gkv, 256, GEMM_SMEM>>>(x, Wv, pv, BT_, KVD_, DIM_);

    rmsrope_kernel<<<dim3(BT_ / 8, NH_ + NKV_), 256>>>(pq, pk);

    attn_kernel<<<dim3(B_ * NH_, T_ / 128), 256, ATT_SMEM>>>(pq, pk, pv, py);

    gemm_mma<<<gq, 256, GEMM_SMEM>>>(py, Wp, out, BT_, DIM_, DIM_);
}

// round 8
// speedup vs baseline: 3.6836x; 1.1377x over previous
#include <cuda_runtime.h>
#include <math.h>
#include <stdint.h>

#define B_   8
#define T_   2048
#define DIM_ 512
#define NH_  8
#define NKV_ 4
#define HD_  64
#define KVD_ 256
#define BT_  (B_ * T_)

__device__ float g_q[BT_ * DIM_];
__device__ float g_k[BT_ * KVD_];
__device__ float g_v[BT_ * KVD_];
__device__ float g_y[BT_ * DIM_];
__device__ float2 g_rope[T_ * 32];     // (cos, sin) per (t, freq-lane)

// ---------------------------------------------------------------------------
// mma.sync m16n8k8 tf32 helpers
// ---------------------------------------------------------------------------
__device__ __forceinline__ uint32_t f2tf32(float x) {
    uint32_t r;
    asm("cvt.rna.tf32.f32 %0, %1;" : "=r"(r) : "f"(x));
    return r;
}
__device__ __forceinline__ float ex2f(float x) {
    float r;
    asm("ex2.approx.ftz.f32 %0, %1;" : "=f"(r) : "f"(x));
    return r;
}
__device__ __forceinline__ void mma_tf32(float* c, uint32_t a0, uint32_t a1,
                                         uint32_t a2, uint32_t a3,
                                         uint32_t b0, uint32_t b1) {
    asm volatile(
        "mma.sync.aligned.m16n8k8.row.col.f32.tf32.tf32.f32 "
        "{%0,%1,%2,%3}, {%4,%5,%6,%7}, {%8,%9}, {%0,%1,%2,%3};"
        : "+f"(c[0]), "+f"(c[1]), "+f"(c[2]), "+f"(c[3])
        : "r"(a0), "r"(a1), "r"(a2), "r"(a3), "r"(b0), "r"(b1));
}
__device__ __forceinline__ uint32_t ldb(const float* p) {
    return __float_as_uint(*p);
}

// ---------------------------------------------------------------------------
// Tensor-core tf32 GEMM: C[M,N] = A[M,K] * B[N,K]^T.  CTA 128x128, K-chunk 32.
// (256,2): 2 CTAs/SM for latency hiding (smem 2*72KB fits; <=6 spill regs).
// ---------------------------------------------------------------------------
#define GST 36
#define GEMM_SMEM (4 * 128 * GST * 4)   // 73728 B

__global__ __launch_bounds__(256, 2) void gemm_mma(const float* __restrict__ A,
                                                   const float* __restrict__ Bm,
                                                   float* __restrict__ C,
                                                   int M, int N, int K) {
    extern __shared__ float sm[];
    const int tid  = threadIdx.x;
    const int warp = tid >> 5;
    const int lane = tid & 31;
    const int gid  = lane >> 2;
    const int qid  = lane & 3;
    const int bm = blockIdx.y << 7;
    const int bn = blockIdx.x << 7;
    const int wm = (warp >> 2) << 6;
    const int wn = (warp & 3) << 5;

    float acc[4][4][4];
#pragma unroll
    for (int mt = 0; mt < 4; mt++)
#pragma unroll
        for (int nt = 0; nt < 4; nt++)
#pragma unroll
            for (int r = 0; r < 4; r++) acc[mt][nt][r] = 0.f;

    const int nch = K >> 5;
    float4 ra[4], rb[4];

#pragma unroll
    for (int i = 0; i < 4; i++) {
        const int idx = (i << 8) + tid, row = idx >> 3, c4 = (idx & 7) << 2;
        ra[i] = *(const float4*)(A  + (size_t)(bm + row) * K + c4);
        rb[i] = *(const float4*)(Bm + (size_t)(bn + row) * K + c4);
    }
    {
        float* As = sm; float* Bs = sm + 128 * GST;
#pragma unroll
        for (int i = 0; i < 4; i++) {
            const int idx = (i << 8) + tid, row = idx >> 3, c4 = (idx & 7) << 2;
            uint4 ua = { f2tf32(ra[i].x), f2tf32(ra[i].y), f2tf32(ra[i].z), f2tf32(ra[i].w) };
            uint4 ub = { f2tf32(rb[i].x), f2tf32(rb[i].y), f2tf32(rb[i].z), f2tf32(rb[i].w) };
            *(uint4*)(As + row * GST + c4) = ua;
            *(uint4*)(Bs + row * GST + c4) = ub;
        }
    }
    __syncthreads();

    for (int kc = 0; kc < nch; kc++) {
        if (kc + 1 < nch) {
            const int k0 = (kc + 1) << 5;
#pragma unroll
            for (int i = 0; i < 4; i++) {
                const int idx = (i << 8) + tid, row = idx >> 3, c4 = (idx & 7) << 2;
                ra[i] = *(const float4*)(A  + (size_t)(bm + row) * K + k0 + c4);
                rb[i] = *(const float4*)(Bm + (size_t)(bn + row) * K + k0 + c4);
            }
        }
        {
            const float* As = sm + (kc & 1) * (2 * 128 * GST);
            const float* Bs = As + 128 * GST;
#pragma unroll
            for (int ks = 0; ks < 4; ks++) {
                uint32_t af[4][4], bf[4][2];
#pragma unroll
                for (int mt = 0; mt < 4; mt++) {
                    const float* ap = As + (wm + mt * 16 + gid) * GST + ks * 8 + qid;
                    af[mt][0] = ldb(ap);
                    af[mt][1] = ldb(ap + 8 * GST);
                    af[mt][2] = ldb(ap + 4);
                    af[mt][3] = ldb(ap + 8 * GST + 4);
                }
#pragma unroll
                for (int nt = 0; nt < 4; nt++) {
                    const float* bp = Bs + (wn + nt * 8 + gid) * GST + ks * 8 + qid;
                    bf[nt][0] = ldb(bp);
                    bf[nt][1] = ldb(bp + 4);
                }
#pragma unroll
                for (int mt = 0; mt < 4; mt++)
#pragma unroll
                    for (int nt = 0; nt < 4; nt++)
                        mma_tf32(acc[mt][nt], af[mt][0], af[mt][1], af[mt][2], af[mt][3],
                                 bf[nt][0], bf[nt][1]);
            }
        }
        if (kc + 1 < nch) {
            __syncthreads();
            float* As = sm + ((kc + 1) & 1) * (2 * 128 * GST);
            float* Bs = As + 128 * GST;
#pragma unroll
            for (int i = 0; i < 4; i++) {
                const int idx = (i << 8) + tid, row = idx >> 3, c4 = (idx & 7) << 2;
                uint4 ua = { f2tf32(ra[i].x), f2tf32(ra[i].y), f2tf32(ra[i].z), f2tf32(ra[i].w) };
                uint4 ub = { f2tf32(rb[i].x), f2tf32(rb[i].y), f2tf32(rb[i].z), f2tf32(rb[i].w) };
                *(uint4*)(As + row * GST + c4) = ua;
                *(uint4*)(Bs + row * GST + c4) = ub;
            }
            __syncthreads();
        }
    }

#pragma unroll
    for (int mt = 0; mt < 4; mt++) {
        const int r0 = bm + wm + mt * 16 + gid;
#pragma unroll
        for (int nt = 0; nt < 4; nt++) {
            const int cc = bn + wn + nt * 8 + 2 * qid;
            *(float2*)(C + (size_t)r0 * N + cc)       = make_float2(acc[mt][nt][0], acc[mt][nt][1]);
            *(float2*)(C + (size_t)(r0 + 8) * N + cc) = make_float2(acc[mt][nt][2], acc[mt][nt][3]);
        }
    }
}

// ---------------------------------------------------------------------------
// RoPE table + RMSNorm/RoPE apply
// ---------------------------------------------------------------------------
__constant__ float c_invfreq[32] = {
    1.0f, 0.7498942093324559f, 0.5623413251903491f, 0.4216965034285822f,
    0.31622776601683794f, 0.23713737056616552f, 0.1778279410038923f, 0.13335214321633242f,
    0.1f, 0.07498942093324558f, 0.05623413251903491f, 0.04216965034285822f,
    0.031622776601683794f, 0.023713737056616554f, 0.01778279410038923f, 0.013335214321633242f,
    0.01f, 0.007498942093324559f, 0.005623413251903491f, 0.004216965034285823f,
    0.0031622776601683794f, 0.0023713737056616554f, 0.001778279410038923f, 0.0013335214321633242f,
    0.001f, 0.0007498942093324558f, 0.0005623413251903491f, 0.0004216965034285822f,
    0.00031622776601683794f, 0.00023713737056616552f, 0.0001778279410038923f, 0.00013335214321633242f
};

__global__ __launch_bounds__(256) void rope_table_kernel() {
    const int idx = blockIdx.x * 256 + threadIdx.x;
    const int t = idx >> 5, lane = idx & 31;
    float s, c;
    sincosf((float)t * c_invfreq[lane], &s, &c);
    g_rope[idx] = make_float2(c, s);
}

__global__ __launch_bounds__(256) void rmsrope_kernel(float* __restrict__ q,
                                                      float* __restrict__ k) {
    const int lane = threadIdx.x & 31;
    const int token = (blockIdx.x << 3) + (threadIdx.x >> 5);
    const int head = blockIdx.y;
    const int t = token & (T_ - 1);

    float* base = (head < NH_)
        ? q + (size_t)token * DIM_ + head * HD_
        : k + (size_t)token * KVD_ + (head - NH_) * HD_;

    float x1 = base[lane];
    float x2 = base[lane + 32];
    float ss = x1 * x1 + x2 * x2;
#pragma unroll
    for (int o = 16; o; o >>= 1) ss += __shfl_xor_sync(0xffffffffu, ss, o);
    const float r = rsqrtf(ss * (1.0f / 64.0f) + 1.1920928955078125e-07f);
    x1 *= r; x2 *= r;

    const float2 cs = g_rope[t * 32 + lane];
    base[lane]      =  x1 * cs.x + x2 * cs.y;
    base[lane + 32] = -x1 * cs.y + x2 * cs.x;
}

// ---------------------------------------------------------------------------
// Flash attention, tf32 mma. 256 threads, q-tile 128, kv-tile 64.
// LPT scheduling: heaviest q-blocks (most kv tiles) launch FIRST, so the
// scheduling tail is made of the cheapest CTAs instead of the costliest.
// ---------------------------------------------------------------------------
#define AST 68
#define ATT_SMEM ((128 + 64 + 64 + 128) * AST * 4)   // 104448 B
#define SCALE2 0.18033688011112042f   // 0.125 * log2(e)

__global__ __launch_bounds__(256, 2) void attn_kernel(const float* __restrict__ q,
                                                      const float* __restrict__ k,
                                                      const float* __restrict__ v,
                                                      float* __restrict__ y) {
    extern __shared__ float sm[];
    float* Qs  = sm;                       // [128][AST]
    float* KsT = Qs + 128 * AST;           // [64 d][AST kv]
    float* Vs  = KsT + 64 * AST;           // [64 kv][AST d]
    float* Ps  = Vs + 64 * AST;            // [128][AST kv]

    const int tid  = threadIdx.x;
    const int warp = tid >> 5;
    const int lane = tid & 31;
    const int gid  = lane >> 2;
    const int qid  = lane & 3;
    const int bh = blockIdx.x;
    const int b  = bh >> 3;
    const int h  = bh & 7;
    const int hk = h >> 1;
    const int qb = (gridDim.y - 1) - blockIdx.y;   // LPT: big work first
    const int q0 = qb << 7;

    const float* qbp = q + ((size_t)(b * T_ + q0)) * DIM_ + h * HD_;
    const float* kb  = k + ((size_t)(b * T_)) * KVD_ + hk * HD_;
    const float* vb  = v + ((size_t)(b * T_)) * KVD_ + hk * HD_;

    // Q tile (tf32 bits)
#pragma unroll
    for (int i = 0; i < 8; i++) {
        const int idx = (i << 8) + tid;
        const int rr = idx >> 4, c4 = (idx & 15) << 2;
        float4 vq = *(const float4*)(qbp + (size_t)rr * DIM_ + c4);
        uint4 uq = { f2tf32(vq.x), f2tf32(vq.y), f2tf32(vq.z), f2tf32(vq.w) };
        *(uint4*)(Qs + rr * AST + c4) = uq;
    }

    const int row0 = q0 + warp * 16 + gid;
    float m_[2], l_[2], o_[8][4];
    m_[0] = m_[1] = -1e30f;
    l_[0] = l_[1] = 0.f;
#pragma unroll
    for (int nt = 0; nt < 8; nt++)
#pragma unroll
        for (int r = 0; r < 4; r++) o_[nt][r] = 0.f;

    const int ntiles = 2 * (qb + 1);
    for (int kt = 0; kt < ntiles; kt++) {
        const int k0 = kt << 6;
        __syncthreads();   // prior PV reads done; Q tile done (iter 0)
#pragma unroll
        for (int i = 0; i < 4; i++) {
            const int idx = (i << 8) + tid;
            const int rr = idx >> 4, c4 = (idx & 15) << 2;
            float4 kk4 = *(const float4*)(kb + (size_t)(k0 + rr) * KVD_ + c4);
            KsT[(c4 + 0) * AST + rr] = __uint_as_float(f2tf32(kk4.x));
            KsT[(c4 + 1) * AST + rr] = __uint_as_float(f2tf32(kk4.y));
            KsT[(c4 + 2) * AST + rr] = __uint_as_float(f2tf32(kk4.z));
            KsT[(c4 + 3) * AST + rr] = __uint_as_float(f2tf32(kk4.w));
            float4 vv4 = *(const float4*)(vb + (size_t)(k0 + rr) * KVD_ + c4);
            uint4 uv = { f2tf32(vv4.x), f2tf32(vv4.y), f2tf32(vv4.z), f2tf32(vv4.w) };
            *(uint4*)(Vs + rr * AST + c4) = uv;
        }
        __syncthreads();

        // S = Q K^T
        float s_[8][4];
#pragma unroll
        for (int nt = 0; nt < 8; nt++)
#pragma unroll
            for (int r = 0; r < 4; r++) s_[nt][r] = 0.f;

#pragma unroll
        for (int ks = 0; ks < 8; ks++) {
            const float* ap = Qs + (warp * 16 + gid) * AST + ks * 8 + qid;
            uint32_t a0 = ldb(ap), a1 = ldb(ap + 8 * AST), a2 = ldb(ap + 4),
                     a3 = ldb(ap + 8 * AST + 4);
#pragma unroll
            for (int nt = 0; nt < 8; nt++) {
                const float* bp = KsT + (ks * 8 + qid) * AST + nt * 8 + gid;
                mma_tf32(s_[nt], a0, a1, a2, a3, ldb(bp), ldb(bp + 4 * AST));
            }
        }

        // scale (base-2) + mask + online softmax
        const bool diag = (kt >= ntiles - 2);
        float mloc[2] = { -1e30f, -1e30f };
#pragma unroll
        for (int nt = 0; nt < 8; nt++) {
            const int cbase = k0 + nt * 8 + 2 * qid;
#pragma unroll
            for (int r = 0; r < 4; r++) {
                float sv = s_[nt][r] * SCALE2;
                if (diag && (cbase + (r & 1) > row0 + 8 * (r >> 1))) sv = -1e30f;
                s_[nt][r] = sv;
                mloc[r >> 1] = fmaxf(mloc[r >> 1], sv);
            }
        }
#pragma unroll
        for (int r = 0; r < 2; r++) {
            mloc[r] = fmaxf(mloc[r], __shfl_xor_sync(0xffffffffu, mloc[r], 1));
            mloc[r] = fmaxf(mloc[r], __shfl_xor_sync(0xffffffffu, mloc[r], 2));
        }
        float alpha[2], sum[2];
#pragma unroll
        for (int r = 0; r < 2; r++) {
            const float mnew = fmaxf(m_[r], mloc[r]);
            alpha[r] = ex2f(m_[r] - mnew);
            m_[r] = mnew;
            sum[r] = 0.f;
        }
#pragma unroll
        for (int nt = 0; nt < 8; nt++) {
#pragma unroll
            for (int r = 0; r < 4; r++) {
                float pv = ex2f(s_[nt][r] - m_[r >> 1]);
                s_[nt][r] = pv;
                sum[r >> 1] += pv;
            }
            float* pp = Ps + (warp * 16 + gid) * AST + nt * 8 + 2 * qid;
            *(float2*)pp = make_float2(__uint_as_float(f2tf32(s_[nt][0])),
                                       __uint_as_float(f2tf32(s_[nt][1])));
            *(float2*)(pp + 8 * AST) = make_float2(__uint_as_float(f2tf32(s_[nt][2])),
                                                   __uint_as_float(f2tf32(s_[nt][3])));
        }
#pragma unroll
        for (int r = 0; r < 2; r++) {
            sum[r] += __shfl_xor_sync(0xffffffffu, sum[r], 1);
            sum[r] += __shfl_xor_sync(0xffffffffu, sum[r], 2);
            l_[r] = l_[r] * alpha[r] + sum[r];
        }
#pragma unroll
        for (int nt = 0; nt < 8; nt++) {
            o_[nt][0] *= alpha[0]; o_[nt][1] *= alpha[0];
            o_[nt][2] *= alpha[1]; o_[nt][3] *= alpha[1];
        }
        __syncwarp();   // P visible to own warp's lanes

        // O += P V
#pragma unroll
        for (int ks = 0; ks < 8; ks++) {
            const float* ap = Ps + (warp * 16 + gid) * AST + ks * 8 + qid;
            uint32_t a0 = ldb(ap), a1 = ldb(ap + 8 * AST), a2 = ldb(ap + 4),
                     a3 = ldb(ap + 8 * AST + 4);
#pragma unroll
            for (int nt = 0; nt < 8; nt++) {
                const float* bp = Vs + (ks * 8 + qid) * AST + nt * 8 + gid;
                mma_tf32(o_[nt], a0, a1, a2, a3, ldb(bp), ldb(bp + 4 * AST));
            }
        }
    }

    const float inv0 = 1.0f / l_[0];
    const float inv1 = 1.0f / l_[1];
    float* y0 = y + (size_t)(b * T_ + row0) * DIM_ + h * HD_;
    float* y1 = y0 + (size_t)8 * DIM_;
#pragma unroll
    for (int nt = 0; nt < 8; nt++) {
        const int cc = nt * 8 + 2 * qid;
        *(float2*)(y0 + cc) = make_float2(o_[nt][0] * inv0, o_[nt][1] * inv0);
        *(float2*)(y1 + cc) = make_float2(o_[nt][2] * inv1, o_[nt][3] * inv1);
    }
}

// ---------------------------------------------------------------------------
extern "C" void kernel_launch(void* const* d_in, const int* in_sizes, int n_in,
                              void* d_out, int out_size) {
    const float* x  = (const float*)d_in[0];
    const float* Wq = (const float*)d_in[1];
    const float* Wk = (const float*)d_in[2];
    const float* Wv = (const float*)d_in[3];
    const float* Wp = (const float*)d_in[4];
    float* out = (float*)d_out;

    float *pq, *pk, *pv, *py;
    cudaGetSymbolAddress((void**)&pq, g_q);
    cudaGetSymbolAddress((void**)&pk, g_k);
    cudaGetSymbolAddress((void**)&pv, g_v);
    cudaGetSymbolAddress((void**)&py, g_y);

    cudaFuncSetAttribute(gemm_mma, cudaFuncAttributeMaxDynamicSharedMemorySize, GEMM_SMEM);
    cudaFuncSetAttribute(attn_kernel, cudaFuncAttributeMaxDynamicSharedMemorySize, ATT_SMEM);

    dim3 gq(DIM_ / 128, BT_ / 128);
    dim3 gkv(KVD_ / 128, BT_ / 128);

    rope_table_kernel<<<T_ * 32 / 256, 256>>>();

    gemm_mma<<<gq, 256, GEMM_SMEM>>>(x, Wq, pq, BT_, DIM_, DIM_);
    gemm_mma<<<gkv, 256, GEMM_SMEM>>>(x, Wk, pk, BT_, KVD_, DIM_);
    gemm_mma<<<gkv, 256, GEMM_SMEM>>>(x, Wv, pv, BT_, KVD_, DIM_);

    rmsrope_kernel<<<dim3(BT_ / 8, NH_ + NKV_), 256>>>(pq, pk);

    attn_kernel<<<dim3(B_ * NH_, T_ / 128), 256, ATT_SMEM>>>(pq, pk, pv, py);

    gemm_mma<<<gq, 256, GEMM_SMEM>>>(py, Wp, out, BT_, DIM_, DIM_);
}